// round 3
// baseline (speedup 1.0000x reference)
#include <cuda_runtime.h>
#include <math.h>

#define Bsz  4096
#define Tt   512
#define INP  25
#define Hh   50
#define Gg   200
#define KTOT 75
#define ROWS 16
#define NTH  200
#define GRID 256          // 256 * 16 = 4096 exactly
#define WS   204          // w_s row stride (padded, floats)
#define XS   20           // xh_s row stride (padded)
#define GS   20           // gates_s row stride (padded)
#define CS   16           // c_s row stride

__device__ __forceinline__ float sigf(float v) {
    return 1.0f / (1.0f + __expf(-v));
}
__device__ __forceinline__ float tanh_fast(float v) {
    return fmaf(2.0f, 1.0f / (1.0f + __expf(-2.0f * v)), -1.0f);
}

__global__ void __launch_bounds__(NTH, 2)
bayes_lstm_kernel(const float* __restrict__ x,
                  const float* __restrict__ wi_mu, const float* __restrict__ wi_rho,
                  const float* __restrict__ wh_mu, const float* __restrict__ wh_rho,
                  const float* __restrict__ b_mu,  const float* __restrict__ b_rho,
                  const float* __restrict__ lin_w, const float* __restrict__ lin_b,
                  const float* __restrict__ eps_wi, const float* __restrict__ eps_wh,
                  const float* __restrict__ eps_b,
                  float* __restrict__ out)
{
    extern __shared__ float sm[];
    float* w_s     = sm;                    // [75][WS]   15300
    float* bias_s  = w_s + KTOT * WS;       // [200]        200
    float* xh_s    = bias_s + Gg;           // [75][XS]    1500 (x rows 0..24, h rows 25..74)
    float* c_s     = xh_s + KTOT * XS;      // [50][CS]     800
    float* gates_s = c_s + Hh * CS;         // [200][GS]   4000

    const int tid  = threadIdx.x;
    const long row0 = (long)blockIdx.x * ROWS;

    // ---- One-time: sample fused weights w = mu + softplus(rho)*eps (padded stride) ----
    for (int i = tid; i < KTOT * Gg; i += NTH) {
        int k = i / Gg, j = i - k * Gg;
        float mu, rho, ep;
        if (i < INP * Gg) { mu = wi_mu[i]; rho = wi_rho[i]; ep = eps_wi[i]; }
        else { int i2 = i - INP * Gg; mu = wh_mu[i2]; rho = wh_rho[i2]; ep = eps_wh[i2]; }
        w_s[k * WS + j] = fmaf(log1pf(__expf(rho)), ep, mu);
    }
    for (int i = tid; i < Gg; i += NTH)
        bias_s[i] = fmaf(log1pf(__expf(b_rho[i])), eps_b[i], b_mu[i]);
    for (int i = tid; i < Hh * XS; i += NTH) xh_s[INP * XS + i] = 0.0f;  // h rows
    for (int i = tid; i < Hh * CS; i += NTH) c_s[i] = 0.0f;
    // x for t=0 (2 elems per thread; 400 = 25*16 total)
    {
        int r = tid / INP, k = tid - r * INP;
        xh_s[k * XS + r] = x[(size_t)(row0 + r) * (Tt * INP) + k];
        int t2 = tid + NTH; int r2 = t2 / INP, k2 = t2 - r2 * INP;
        xh_s[k2 * XS + r2] = x[(size_t)(row0 + r2) * (Tt * INP) + k2];
    }
    __syncthreads();

    // ---- Gate task map: tile 8j x 8r, K split 4 ways (k ≡ ks mod 4) ----
    const int ks   = tid & 3;
    const int tile = tid >> 2;         // 0..49
    const int rg   = tile & 1;         // rg fastest -> weight-load broadcast in warp
    const int jg   = tile >> 1;        // 0..24
    const int j0   = jg * 8;
    const int r0   = rg * 8;
    const unsigned shmask = (tid >= 192) ? 0x000000FFu : 0xFFFFFFFFu;
    const bool hi1 = (ks & 1) != 0;
    const bool hi2 = (ks & 2) != 0;
    const int  jf  = j0 + (hi1 ? 4 : 0) + (hi2 ? 2 : 0);   // final owned gate rows jf, jf+1

    // bias preloaded once; injected on ks==0 lanes, flows through the reduction
    float bias_r[8];
    #pragma unroll
    for (int u = 0; u < 8; u++) bias_r[u] = (ks == 0) ? bias_s[j0 + u] : 0.0f;

    // x prefetch map
    const int pr0 = tid / INP, pk0 = tid - pr0 * INP;
    const int t2g = tid + NTH;
    const int pr1 = t2g / INP, pk1 = t2g - pr1 * INP;
    const size_t xb0 = (size_t)(row0 + pr0) * (Tt * INP) + pk0;
    const size_t xb1 = (size_t)(row0 + pr1) * (Tt * INP) + pk1;

    // epilogue map: 4 consecutive r of one h column per thread (800 = 200*4)
    const int hcol = tid >> 2;         // 0..49
    const int er0  = (tid & 3) * 4;    // 0,4,8,12

    const float* wp = w_s  + ks * WS + j0;
    const float* vp = xh_s + ks * XS + r0;

    for (int t = 0; t < Tt; ++t) {
        float pf0 = 0.f, pf1 = 0.f;
        if (t + 1 < Tt) {
            pf0 = x[xb0 + (size_t)(t + 1) * INP];
            pf1 = x[xb1 + (size_t)(t + 1) * INP];
        }

        float acc[8][8];
        #pragma unroll
        for (int u = 0; u < 8; u++)
            #pragma unroll
            for (int v = 0; v < 8; v++) acc[u][v] = (v == 0) ? bias_r[u] : 0.0f;
        // note: bias belongs once per (j); spread it on v==0 only? No — bias is per
        // output element (j,r): every r needs it. Put it on all v:
        #pragma unroll
        for (int u = 0; u < 8; u++)
            #pragma unroll
            for (int v = 1; v < 8; v++) acc[u][v] = bias_r[u];

        #pragma unroll 1
        for (int i = 0; i < 18; i++) {
            const float* wk = wp + (4 * i) * WS;
            const float* vk = vp + (4 * i) * XS;
            float4 wa = *(const float4*)(wk);
            float4 wb = *(const float4*)(wk + 4);
            float4 va = *(const float4*)(vk);
            float4 vb = *(const float4*)(vk + 4);
            float wr[8] = {wa.x, wa.y, wa.z, wa.w, wb.x, wb.y, wb.z, wb.w};
            float vr[8] = {va.x, va.y, va.z, va.w, vb.x, vb.y, vb.z, vb.w};
            #pragma unroll
            for (int u = 0; u < 8; u++)
                #pragma unroll
                for (int v = 0; v < 8; v++)
                    acc[u][v] = fmaf(wr[u], vr[v], acc[u][v]);
        }
        if (ks < 3) {  // tail: k = ks + 72 (< 75 only for ks 0..2)
            const float* wk = wp + 72 * WS;
            const float* vk = vp + 72 * XS;
            float4 wa = *(const float4*)(wk);
            float4 wb = *(const float4*)(wk + 4);
            float4 va = *(const float4*)(vk);
            float4 vb = *(const float4*)(vk + 4);
            float wr[8] = {wa.x, wa.y, wa.z, wa.w, wb.x, wb.y, wb.z, wb.w};
            float vr[8] = {va.x, va.y, va.z, va.w, vb.x, vb.y, vb.z, vb.w};
            #pragma unroll
            for (int u = 0; u < 8; u++)
                #pragma unroll
                for (int v = 0; v < 8; v++)
                    acc[u][v] = fmaf(wr[u], vr[v], acc[u][v]);
        }

        // ---- Split-K reduction: recursive halving (48 SHFL/thread) ----
        // Round 1 (xor 1): even ks keep j-offsets 0-3, give 4-7.
        #pragma unroll
        for (int u = 0; u < 4; u++)
            #pragma unroll
            for (int v = 0; v < 8; v++) {
                float g = hi1 ? acc[u][v] : acc[u + 4][v];
                float p = __shfl_xor_sync(shmask, g, 1);
                acc[u][v]     += hi1 ? 0.0f : p;
                acc[u + 4][v] += hi1 ? p : 0.0f;
            }
        // Round 2 (xor 2): within kept half, keep first 2 rows, give next 2.
        #pragma unroll
        for (int u = 0; u < 2; u++)
            #pragma unroll
            for (int v = 0; v < 8; v++) {
                float gl = hi2 ? acc[u][v]     : acc[u + 2][v];
                float gh = hi2 ? acc[u + 4][v] : acc[u + 6][v];
                float g  = hi1 ? gh : gl;
                float p  = __shfl_xor_sync(shmask, g, 2);
                acc[u][v]     += (!hi1 && !hi2) ? p : 0.0f;
                acc[u + 2][v] += (!hi1 &&  hi2) ? p : 0.0f;
                acc[u + 4][v] += ( hi1 && !hi2) ? p : 0.0f;
                acc[u + 6][v] += ( hi1 &&  hi2) ? p : 0.0f;
            }
        // Owner (lane ks) stores gate rows jf, jf+1 (8 r values each)
        {
            float f0[8], f1[8];
            #pragma unroll
            for (int v = 0; v < 8; v++) {
                f0[v] = hi1 ? (hi2 ? acc[6][v] : acc[4][v])
                            : (hi2 ? acc[2][v] : acc[0][v]);
                f1[v] = hi1 ? (hi2 ? acc[7][v] : acc[5][v])
                            : (hi2 ? acc[3][v] : acc[1][v]);
            }
            *(float4*)(gates_s + jf * GS + r0)           = make_float4(f0[0], f0[1], f0[2], f0[3]);
            *(float4*)(gates_s + jf * GS + r0 + 4)       = make_float4(f0[4], f0[5], f0[6], f0[7]);
            *(float4*)(gates_s + (jf + 1) * GS + r0)     = make_float4(f1[0], f1[1], f1[2], f1[3]);
            *(float4*)(gates_s + (jf + 1) * GS + r0 + 4) = make_float4(f1[4], f1[5], f1[6], f1[7]);
        }
        __syncthreads();   // gates visible; all xh reads of step t complete

        // commit prefetched x(t+1) into xh x-rows
        if (t + 1 < Tt) {
            xh_s[pk0 * XS + pr0] = pf0;
            xh_s[pk1 * XS + pr1] = pf1;
        }

        // ---- Epilogue: 4 elements per thread ----
        {
            float4 gi = *(const float4*)(gates_s + hcol * GS + er0);
            float4 gf = *(const float4*)(gates_s + (hcol + Hh) * GS + er0);
            float4 gg = *(const float4*)(gates_s + (hcol + 2 * Hh) * GS + er0);
            float4 go = *(const float4*)(gates_s + (hcol + 3 * Hh) * GS + er0);
            float4 cc = *(const float4*)(c_s + hcol * CS + er0);
            float4 cn, hn;
            cn.x = fmaf(sigf(gf.x), cc.x, sigf(gi.x) * tanh_fast(gg.x));
            cn.y = fmaf(sigf(gf.y), cc.y, sigf(gi.y) * tanh_fast(gg.y));
            cn.z = fmaf(sigf(gf.z), cc.z, sigf(gi.z) * tanh_fast(gg.z));
            cn.w = fmaf(sigf(gf.w), cc.w, sigf(gi.w) * tanh_fast(gg.w));
            hn.x = sigf(go.x) * tanh_fast(cn.x);
            hn.y = sigf(go.y) * tanh_fast(cn.y);
            hn.z = sigf(go.z) * tanh_fast(cn.z);
            hn.w = sigf(go.w) * tanh_fast(cn.w);
            *(float4*)(c_s + hcol * CS + er0) = cn;
            *(float4*)(xh_s + (INP + hcol) * XS + er0) = hn;
        }
        __syncthreads();   // h, c, x(t+1) ready
    }

    // ---- Head ----
    if (tid < ROWS) {
        float s = lin_b[0];
        #pragma unroll
        for (int m = 0; m < Hh; m++)
            s = fmaf(xh_s[(INP + m) * XS + tid], lin_w[m], s);
        out[row0 + tid] = s;
    }
}

extern "C" void kernel_launch(void* const* d_in, const int* in_sizes, int n_in,
                              void* d_out, int out_size)
{
    const size_t smem_bytes =
        (size_t)(KTOT * WS + Gg + KTOT * XS + Hh * CS + Gg * GS) * sizeof(float); // 87200 B
    cudaFuncSetAttribute(bayes_lstm_kernel,
                         cudaFuncAttributeMaxDynamicSharedMemorySize,
                         (int)smem_bytes);
    bayes_lstm_kernel<<<GRID, NTH, smem_bytes>>>(
        (const float*)d_in[0],  (const float*)d_in[1],  (const float*)d_in[2],
        (const float*)d_in[3],  (const float*)d_in[4],  (const float*)d_in[5],
        (const float*)d_in[6],  (const float*)d_in[7],  (const float*)d_in[8],
        (const float*)d_in[9],  (const float*)d_in[10], (const float*)d_in[11],
        (float*)d_out);
}